// round 11
// baseline (speedup 1.0000x reference)
#include <cuda_runtime.h>
#include <math.h>

#define NODE   5
#define FML    64
#define F0C    256
#define F1C    256
#define FOC    256
#define TSTEPS 128
#define BTOT   8192
#define MROWS  64
#define NCTA   (BTOT / MROWS)   // 128
#define NTHR   256
#define BN_EPS 1e-5f
#define H2LD   260              // padded h2 row stride (floats)

// Scratch (static device arrays: allocation-free)
__device__ float g_h[BTOT * FOC];       // post-ReLU head activations (B,256)
__device__ float g_stats[2 * FOC];      // [0:256) sum, [256:512) sumsq
__device__ float g_xT[TSTEPS * NODE * BTOT];   // x transposed to [t][n][b]

// k-pair interleaved weights: W'[.. kp ..][c][2] with j index = k parity
__device__ __align__(16) float W1i[NODE * 65 * 512];    // [n][kp<65][c<256][2]
__device__ __align__(16) float W2i[NODE * 128 * 512];   // [n][kp<128][c<256][2]
__device__ __align__(16) float W3i[NODE * 128 * 128];   // [n][kp<128][c<64][2]
__device__ __align__(16) float Wo1i[160 * 512];         // [kp<160][c<256][2] (rows 5..324)

__device__ __host__ __forceinline__ constexpr int par0(int n) {
    return n == 0 ? 3 : n == 1 ? 0 : n == 2 ? 0 : n == 3 ? 1 : 2;
}
__device__ __host__ __forceinline__ constexpr int par1(int n) {
    return n == 0 ? 4 : n == 1 ? 4 : n == 2 ? 1 : n == 3 ? 2 : 3;
}

typedef unsigned long long u64;

struct Smem {
    float slot[6][MROWS][FML];   // 98304 B : rotating state arena (6 slots)
    float h1[MROWS][F0C];        // 65536 B
    float h2[MROWS][H2LD];       // 66560 B
    float xs[NODE][MROWS];       //  1280 B
};                               // total 231680 B (<= 227 KB)

__device__ __forceinline__ void ffma2(u64& d, u64 a, u64 b) {
    asm("fma.rn.f32x2 %0, %1, %2, %0;" : "+l"(d) : "l"(a), "l"(b));
}
__device__ __forceinline__ u64 packf(float lo, float hi) {
    u64 r;
    asm("mov.b64 %0, {%1, %2};" : "=l"(r) : "r"(__float_as_uint(lo)), "r"(__float_as_uint(hi)));
    return r;
}
__device__ __forceinline__ float hadd(u64 v) {
    union { u64 u; float f[2]; } t; t.u = v;
    return t.f[0] + t.f[1];
}

// one kpair x 8 cols of interleaved B: 4 LDG.128
struct B8 { ulonglong2 q0, q1, q2, q3; };
__device__ __forceinline__ B8 ldB8(const float* __restrict__ p) {
    B8 r;
    r.q0 = *(const ulonglong2*)(p);
    r.q1 = *(const ulonglong2*)(p + 4);
    r.q2 = *(const ulonglong2*)(p + 8);
    r.q3 = *(const ulonglong2*)(p + 12);
    return r;
}

__device__ __forceinline__ void kp8(u64 (&acc)[8][8], u64 ak, const B8& b, int r) {
    ffma2(acc[r][0], ak, b.q0.x); ffma2(acc[r][1], ak, b.q0.y);
    ffma2(acc[r][2], ak, b.q1.x); ffma2(acc[r][3], ak, b.q1.y);
    ffma2(acc[r][4], ak, b.q2.x); ffma2(acc[r][5], ak, b.q2.y);
    ffma2(acc[r][6], ak, b.q3.x); ffma2(acc[r][7], ak, b.q3.y);
}

// acc[8 rows][8 cols] (each u64 = {even-k sum, odd-k sum}) over nkp kpairs.
// A rows in smem (pairs contiguous), B interleaved in gmem. 2-deep prefetch.
__device__ __forceinline__ void mac_i8(u64 (&acc)[8][8],
    const float* __restrict__ A, int lda,
    const float* __restrict__ B, int ldbi, int nkp)
{
    B8 b0 = ldB8(B);
    B8 b1 = ldB8(B + ldbi);
#pragma unroll 2
    for (int kp = 0; kp < nkp; ++kp) {
        const int kn = (kp + 2 < nkp) ? kp + 2 : kp;
        B8 nx = ldB8(B + (size_t)kn * ldbi);
#pragma unroll
        for (int r = 0; r < 8; ++r) {
            const u64 ak = *(const u64*)(A + (size_t)r * lda + 2 * kp);
            kp8(acc, ak, b0, r);
        }
        b0 = b1; b1 = nx;
    }
}

// 2-row variant (layer 3)
__device__ __forceinline__ void mac_i2(u64 (&acc)[2][8],
    const float* __restrict__ A, int lda,
    const float* __restrict__ B, int ldbi, int nkp)
{
    B8 b0 = ldB8(B);
    B8 b1 = ldB8(B + ldbi);
#pragma unroll 2
    for (int kp = 0; kp < nkp; ++kp) {
        const int kn = (kp + 2 < nkp) ? kp + 2 : kp;
        B8 nx = ldB8(B + (size_t)kn * ldbi);
#pragma unroll
        for (int r = 0; r < 2; ++r) {
            const u64 ak = *(const u64*)(A + (size_t)r * lda + 2 * kp);
            ffma2(acc[r][0], ak, b0.q0.x); ffma2(acc[r][1], ak, b0.q0.y);
            ffma2(acc[r][2], ak, b0.q1.x); ffma2(acc[r][3], ak, b0.q1.y);
            ffma2(acc[r][4], ak, b0.q2.x); ffma2(acc[r][5], ak, b0.q2.y);
            ffma2(acc[r][6], ak, b0.q3.x); ffma2(acc[r][7], ak, b0.q3.y);
        }
        b0 = b1; b1 = nx;
    }
}

// ---------- prep: interleave weights, transpose x, zero stats ----------
__global__ void prep_kernel(const float* __restrict__ x,
                            const float* __restrict__ W1, const float* __restrict__ W2,
                            const float* __restrict__ W3, const float* __restrict__ Wo1)
{
    const int i = blockIdx.x * blockDim.x + threadIdx.x;
    const int stride = gridDim.x * blockDim.x;

    for (int idx = i; idx < NODE * 65 * 512; idx += stride) {
        const int j = idx & 1, c = (idx >> 1) & 255;
        const int nk = idx >> 9, kp = nk % 65, n = nk / 65;
        W1i[idx] = W1[(size_t)n * 130 * 256 + (2 * kp + j) * 256 + c];
    }
    for (int idx = i; idx < NODE * 128 * 512; idx += stride) {
        const int j = idx & 1, c = (idx >> 1) & 255;
        const int nk = idx >> 9, kp = nk & 127, n = nk >> 7;
        W2i[idx] = W2[(size_t)n * 65536 + (2 * kp + j) * 256 + c];
    }
    for (int idx = i; idx < NODE * 128 * 128; idx += stride) {
        const int j = idx & 1, c = (idx >> 1) & 63;
        const int nk = idx >> 7, kp = nk & 127, n = nk >> 7;
        W3i[idx] = W3[(size_t)n * 16384 + (2 * kp + j) * 64 + c];
    }
    for (int idx = i; idx < 160 * 512; idx += stride) {
        const int j = idx & 1, c = (idx >> 1) & 255, kp = idx >> 9;
        Wo1i[idx] = Wo1[(size_t)(5 + 2 * kp + j) * 256 + c];
    }
    for (int idx = i; idx < TSTEPS * NODE * BTOT; idx += stride) {
        const int b = idx & (BTOT - 1), nt = idx >> 13;
        const int n = nt % NODE, t = nt / NODE;
        g_xT[idx] = x[(size_t)b * (NODE * TSTEPS) + n * TSTEPS + t];
    }
    if (i < 2 * FOC) g_stats[i] = 0.0f;
}

__global__ __launch_bounds__(NTHR, 1)
void rnn_kernel(const float* __restrict__ b1, const float* __restrict__ b2,
                const float* __restrict__ b3, const float* __restrict__ Wo1,
                const float* __restrict__ bo1)
{
    extern __shared__ char smem_raw[];
    Smem& S = *reinterpret_cast<Smem*>(smem_raw);
    const int tid = threadIdx.x;
    const int tx  = tid & 31;
    const int w   = tid >> 5;         // warp 0..7 -> column slice
    const int cg  = tx & 3;
    const int rg  = tx >> 2;
    const int r0  = rg * 8;           // lane's 8 rows
    const int c0  = w * 32 + cg * 8;  // lane's 8 cols (L1/L2/head)
    const int c3  = w * 8;            // L3: warp's 8 cols
    const int lr  = tx * 2;           // L3: lane's 2 rows
    const int b0  = blockIdx.x * MROWS;

    for (int i = tid; i < 6 * MROWS * FML; i += NTHR)
        (&S.slot[0][0][0])[i] = 0.0f;
    __syncthreads();

    int sl[6] = {0, 1, 2, 3, 4, 5};

    for (int t = 0; t < TSTEPS; ++t) {
        for (int i = tid; i < NODE * MROWS; i += NTHR) {
            const int n = i >> 6, r = i & 63;
            S.xs[n][r] = g_xT[((size_t)t * NODE + n) * BTOT + b0 + r];
        }
        __syncthreads();

#pragma unroll
        for (int n = 0; n < NODE; ++n) {
            const int p0 = par0(n), p1 = par1(n);
            const float* W1n = W1i + (size_t)n * 65 * 512;
            const float* sp0 = &S.slot[sl[p0]][0][0];
            const float* sp1 = &S.slot[sl[p1]][0][0];

            // ---------- Layer 1: inp(130) -> 256, ReLU ----------
            u64 acc[8][8];
#pragma unroll
            for (int r = 0; r < 8; ++r)
#pragma unroll
                for (int c = 0; c < 8; ++c) acc[r][c] = 0ull;
            {   // kpair 0 = the two x inputs
                const B8 bx = ldB8(W1n + c0 * 2);
#pragma unroll
                for (int r = 0; r < 8; ++r) {
                    const u64 xab = packf(S.xs[p0][r0 + r], S.xs[p1][r0 + r]);
                    kp8(acc, xab, bx, r);
                }
            }
            mac_i8(acc, sp0 + (size_t)r0 * FML, FML, W1n + 512 + c0 * 2, 512, 32);
            mac_i8(acc, sp1 + (size_t)r0 * FML, FML, W1n + 33 * 512 + c0 * 2, 512, 32);
            {
                const float4 bb0 = *(const float4*)(b1 + n * F0C + c0);
                const float4 bb1 = *(const float4*)(b1 + n * F0C + c0 + 4);
#pragma unroll
                for (int r = 0; r < 8; ++r) {
                    *(float4*)&S.h1[r0 + r][c0] = make_float4(
                        fmaxf(hadd(acc[r][0]) + bb0.x, 0.f),
                        fmaxf(hadd(acc[r][1]) + bb0.y, 0.f),
                        fmaxf(hadd(acc[r][2]) + bb0.z, 0.f),
                        fmaxf(hadd(acc[r][3]) + bb0.w, 0.f));
                    *(float4*)&S.h1[r0 + r][c0 + 4] = make_float4(
                        fmaxf(hadd(acc[r][4]) + bb1.x, 0.f),
                        fmaxf(hadd(acc[r][5]) + bb1.y, 0.f),
                        fmaxf(hadd(acc[r][6]) + bb1.z, 0.f),
                        fmaxf(hadd(acc[r][7]) + bb1.w, 0.f));
                }
            }
            __syncthreads();

            // ---------- Layer 2: 256 -> 256, ReLU ----------
#pragma unroll
            for (int r = 0; r < 8; ++r)
#pragma unroll
                for (int c = 0; c < 8; ++c) acc[r][c] = 0ull;
            mac_i8(acc, &S.h1[r0][0], F0C,
                   W2i + (size_t)n * 128 * 512 + c0 * 2, 512, 128);
            {
                const float4 bb0 = *(const float4*)(b2 + n * F1C + c0);
                const float4 bb1 = *(const float4*)(b2 + n * F1C + c0 + 4);
#pragma unroll
                for (int r = 0; r < 8; ++r) {
                    *(float4*)&S.h2[r0 + r][c0] = make_float4(
                        fmaxf(hadd(acc[r][0]) + bb0.x, 0.f),
                        fmaxf(hadd(acc[r][1]) + bb0.y, 0.f),
                        fmaxf(hadd(acc[r][2]) + bb0.z, 0.f),
                        fmaxf(hadd(acc[r][3]) + bb0.w, 0.f));
                    *(float4*)&S.h2[r0 + r][c0 + 4] = make_float4(
                        fmaxf(hadd(acc[r][4]) + bb1.x, 0.f),
                        fmaxf(hadd(acc[r][5]) + bb1.y, 0.f),
                        fmaxf(hadd(acc[r][6]) + bb1.z, 0.f),
                        fmaxf(hadd(acc[r][7]) + bb1.w, 0.f));
                }
            }
            __syncthreads();

            // ---------- Layer 3: 256 -> 64, tanh -> state slot ----------
            {
                u64 a2[2][8];
#pragma unroll
                for (int r = 0; r < 2; ++r)
#pragma unroll
                    for (int c = 0; c < 8; ++c) a2[r][c] = 0ull;
                mac_i2(a2, &S.h2[lr][0], H2LD,
                       W3i + (size_t)n * 128 * 128 + c3 * 2, 128, 128);
                const int ds = (n == 0) ? sl[5] : (n == 1) ? sl[4] : sl[n - 2];
                float* dst = &S.slot[ds][0][0];
                const float4 bb0 = *(const float4*)(b3 + n * FML + c3);
                const float4 bb1 = *(const float4*)(b3 + n * FML + c3 + 4);
#pragma unroll
                for (int r = 0; r < 2; ++r) {
                    *(float4*)&dst[(size_t)(lr + r) * FML + c3] = make_float4(
                        tanhf(hadd(a2[r][0]) + bb0.x), tanhf(hadd(a2[r][1]) + bb0.y),
                        tanhf(hadd(a2[r][2]) + bb0.z), tanhf(hadd(a2[r][3]) + bb0.w));
                    *(float4*)&dst[(size_t)(lr + r) * FML + c3 + 4] = make_float4(
                        tanhf(hadd(a2[r][4]) + bb1.x), tanhf(hadd(a2[r][5]) + bb1.y),
                        tanhf(hadd(a2[r][6]) + bb1.z), tanhf(hadd(a2[r][7]) + bb1.w));
                }
            }
            __syncthreads();
        }

        {   // rotate slot map
            const int t0 = sl[0], t1 = sl[1], t2 = sl[2];
            const int t3 = sl[3], t4 = sl[4], t5 = sl[5];
            sl[0] = t5; sl[1] = t4; sl[2] = t0;
            sl[3] = t1; sl[4] = t2; sl[5] = t3;
        }
    }

    // ---------- Head GEMM: feat(325) @ Wo1 -> ReLU -> g_h + BN partials ----------
    float* red = &S.h1[0][0];
    for (int i = tid; i < 2 * FOC; i += NTHR) red[i] = 0.0f;
    __syncthreads();

    {
        u64 acc[8][8];
#pragma unroll
        for (int r = 0; r < 8; ++r)
#pragma unroll
            for (int c = 0; c < 8; ++c) acc[r][c] = 0ull;
#pragma unroll
        for (int n = 0; n < NODE; ++n)
            mac_i8(acc, &S.slot[sl[n]][r0][0], FML,
                   Wo1i + (size_t)n * 32 * 512 + c0 * 2, 512, 32);

        float v[8][8];
        {
            const float4 bb0 = *(const float4*)(bo1 + c0);
            const float4 bb1 = *(const float4*)(bo1 + c0 + 4);
#pragma unroll
            for (int r = 0; r < 8; ++r) {
                v[r][0] = hadd(acc[r][0]) + bb0.x; v[r][1] = hadd(acc[r][1]) + bb0.y;
                v[r][2] = hadd(acc[r][2]) + bb0.z; v[r][3] = hadd(acc[r][3]) + bb0.w;
                v[r][4] = hadd(acc[r][4]) + bb1.x; v[r][5] = hadd(acc[r][5]) + bb1.y;
                v[r][6] = hadd(acc[r][6]) + bb1.z; v[r][7] = hadd(acc[r][7]) + bb1.w;
            }
        }
#pragma unroll
        for (int n = 0; n < NODE; ++n) {   // scalar x part (rows 0..4 of Wo1)
            const float4 w0 = *(const float4*)(Wo1 + n * FOC + c0);
            const float4 w1 = *(const float4*)(Wo1 + n * FOC + c0 + 4);
#pragma unroll
            for (int r = 0; r < 8; ++r) {
                const float xv = S.xs[n][r0 + r];   // xs holds t = T-1
                v[r][0] = fmaf(xv, w0.x, v[r][0]); v[r][1] = fmaf(xv, w0.y, v[r][1]);
                v[r][2] = fmaf(xv, w0.z, v[r][2]); v[r][3] = fmaf(xv, w0.w, v[r][3]);
                v[r][4] = fmaf(xv, w1.x, v[r][4]); v[r][5] = fmaf(xv, w1.y, v[r][5]);
                v[r][6] = fmaf(xv, w1.z, v[r][6]); v[r][7] = fmaf(xv, w1.w, v[r][7]);
            }
        }
        float cs[8] = {0,0,0,0,0,0,0,0};
        float cq[8] = {0,0,0,0,0,0,0,0};
#pragma unroll
        for (int r = 0; r < 8; ++r) {
            float vv[8];
#pragma unroll
            for (int j = 0; j < 8; ++j) {
                vv[j] = fmaxf(v[r][j], 0.f);
                cs[j] += vv[j];
                cq[j] += vv[j] * vv[j];
            }
            *(float4*)&g_h[(size_t)(b0 + r0 + r) * FOC + c0] =
                make_float4(vv[0], vv[1], vv[2], vv[3]);
            *(float4*)&g_h[(size_t)(b0 + r0 + r) * FOC + c0 + 4] =
                make_float4(vv[4], vv[5], vv[6], vv[7]);
        }
#pragma unroll
        for (int j = 0; j < 8; ++j) {
            atomicAdd(&red[c0 + j],       cs[j]);
            atomicAdd(&red[FOC + c0 + j], cq[j]);
        }
    }
    __syncthreads();
    if (tid < FOC) {
        atomicAdd(&g_stats[tid],       red[tid]);
        atomicAdd(&g_stats[FOC + tid], red[FOC + tid]);
    }
}

// ---------- BN + logits + softmax ----------
__global__ __launch_bounds__(256)
void head_kernel(const float* __restrict__ gamma, const float* __restrict__ beta,
                 const float* __restrict__ Wo2, const float* __restrict__ bo2,
                 float* __restrict__ out)
{
    __shared__ float s_scale[FOC];
    __shared__ float s_shift[FOC];
    __shared__ float s_w[FOC * 7];
    __shared__ float s_b[7];
    const int tid = threadIdx.x;

    if (tid < FOC) {
        const float inv = 1.0f / (float)BTOT;
        float mu  = g_stats[tid] * inv;
        float var = g_stats[FOC + tid] * inv - mu * mu;
        float sc  = gamma[tid] * rsqrtf(var + BN_EPS);
        s_scale[tid] = sc;
        s_shift[tid] = beta[tid] - mu * sc;
    }
    for (int i = tid; i < FOC * 7; i += 256) s_w[i] = Wo2[i];
    if (tid < 7) s_b[tid] = bo2[tid];
    __syncthreads();

    const int lane = tid & 31;
    const int warp = tid >> 5;
    const int row  = blockIdx.x * 8 + warp;

    float l[7] = {0, 0, 0, 0, 0, 0, 0};
#pragma unroll
    for (int ii = 0; ii < 8; ++ii) {
        const int c = lane + 32 * ii;
        const float v  = g_h[(size_t)row * FOC + c];
        const float hn = fmaf(v, s_scale[c], s_shift[c]);
#pragma unroll
        for (int j = 0; j < 7; ++j) l[j] = fmaf(hn, s_w[c * 7 + j], l[j]);
    }
#pragma unroll
    for (int off = 16; off > 0; off >>= 1) {
#pragma unroll
        for (int j = 0; j < 7; ++j) l[j] += __shfl_xor_sync(0xFFFFFFFFu, l[j], off);
    }
    if (lane == 0) {
        float m = -1e30f;
#pragma unroll
        for (int j = 0; j < 7; ++j) { l[j] += s_b[j]; m = fmaxf(m, l[j]); }
        float e[7], sum = 0.f;
#pragma unroll
        for (int j = 0; j < 7; ++j) { e[j] = expf(l[j] - m); sum += e[j]; }
        const float r = 1.0f / sum;
#pragma unroll
        for (int j = 0; j < 7; ++j) out[(size_t)row * 7 + j] = e[j] * r;
    }
}

extern "C" void kernel_launch(void* const* d_in, const int* in_sizes, int n_in,
                              void* d_out, int out_size)
{
    (void)in_sizes; (void)n_in; (void)out_size;
    const float* x    = (const float*)d_in[0];
    const float* W1   = (const float*)d_in[1];
    const float* b1   = (const float*)d_in[2];
    const float* W2   = (const float*)d_in[3];
    const float* b2   = (const float*)d_in[4];
    const float* W3   = (const float*)d_in[5];
    const float* b3   = (const float*)d_in[6];
    const float* Wo1  = (const float*)d_in[7];
    const float* bo1  = (const float*)d_in[8];
    const float* gam  = (const float*)d_in[9];
    const float* bet  = (const float*)d_in[10];
    const float* Wo2  = (const float*)d_in[11];
    const float* bo2  = (const float*)d_in[12];
    float* out = (float*)d_out;

    cudaFuncSetAttribute(rnn_kernel, cudaFuncAttributeMaxDynamicSharedMemorySize,
                         (int)sizeof(Smem));

    prep_kernel<<<512, 256>>>(x, W1, W2, W3, Wo1);
    rnn_kernel<<<NCTA, NTHR, sizeof(Smem)>>>(b1, b2, b3, Wo1, bo1);
    head_kernel<<<BTOT / 8, 256>>>(gam, bet, Wo2, bo2, out);
}